// round 12
// baseline (speedup 1.0000x reference)
#include <cuda_runtime.h>

// Soft 5x5 dilation:  y = logsumexp((w + patch)*B)/B
// Two-kernel split:
//   prep: E = exp2(c*x) into padded 132x132 scratch (halo = 1.0 = exp(0)),
//         taps A = exp2(c*w) pre-duplicated into float2 pairs.
//   conv: direct-LDG 5x5 conv of E (no smem, no barriers, no branches),
//         y = lg2(S) * ln2/B.  Packed fma.rn.f32x2 core.

#define KK 5
#define BETA 15.0f
#define CC 64
#define HH 128
#define WW 128
#define BB 4

#define EP 132                  // padded edge (2 halo each side)
#define EIMG (EP * EP)          // 17424 floats per image
#define NT 128

#define B_LOG2E (BETA * 1.44269504f)
#define LN2_OVER_B (0.69314718f / BETA)

typedef unsigned long long u64;

__device__ float  g_E[(size_t)BB * CC * EIMG];   // ~17.8 MB scratch
__device__ float2 g_A2[CC][32];                  // exp'd taps, lane-duplicated

__device__ __forceinline__ float fast_ex2(float v) {
    float r; asm("ex2.approx.ftz.f32 %0, %1;" : "=f"(r) : "f"(v)); return r;
}
__device__ __forceinline__ float fast_lg2(float v) {
    float r; asm("lg2.approx.ftz.f32 %0, %1;" : "=f"(r) : "f"(v)); return r;
}

union F2U { float2 f; u64 u; };
__device__ __forceinline__ float2 ffma2(float2 a, float2 b, float2 c) {
    F2U A, B, C, D; A.f = a; B.f = b; C.f = c;
    asm("fma.rn.f32x2 %0, %1, %2, %3;" : "=l"(D.u) : "l"(A.u), "l"(B.u), "l"(C.u));
    return D.f;
}

// ── prep: exp-space image + halos + taps ─────────────────────────────────
__global__ __launch_bounds__(NT)
void morph_prep_kernel(const float* __restrict__ x,
                       const float* __restrict__ wy)
{
    const int img  = blockIdx.y;            // b*C + c
    const int band = blockIdx.x;            // 16-row band
    const int t    = threadIdx.x;
    const int lane = t & 31;
    const int r0   = t >> 5;

    const float* xi = x + (size_t)img * (HH * WW);
    float*       Ei = g_E + (size_t)img * EIMG;

    // hoisted loads: 4 rows per thread (MLP=4)
    float4 v[4];
    #pragma unroll
    for (int i = 0; i < 4; i++) {
        int r = band * 16 + r0 * 4 + i;
        v[i] = *(const float4*)&xi[r * WW + 4 * lane];
    }

    // taps (img 0..63 cover every channel once)
    if (band == 0 && img < CC && t < KK * KK) {
        float w0 = fast_ex2(B_LOG2E * wy[img * KK * KK + t]);
        g_A2[img][t] = make_float2(w0, w0);
    }
    // side halo cols 0,1,130,131 for this band's 16 interior rows
    if (t < 32) {
        int rl = t >> 1;
        int cb = (t & 1) ? 130 : 0;
        float* p = &Ei[(band * 16 + rl + 2) * EP + cb];
        p[0] = 1.0f; p[1] = 1.0f;
    }
    // top/bottom halo rows (2 full rows each = 66 float4)
    if (band == 0 && t < 66) ((float4*)Ei)[t] = make_float4(1.f, 1.f, 1.f, 1.f);
    if (band == 7 && t < 66) ((float4*)(Ei + 130 * EP))[t] = make_float4(1.f, 1.f, 1.f, 1.f);

    // convert + store interior (E row = x row + 2, E col = x col + 2)
    #pragma unroll
    for (int i = 0; i < 4; i++) {
        int r = band * 16 + r0 * 4 + i;
        float* d = &Ei[(r + 2) * EP + 4 * lane + 2];
        *(float2*)d       = make_float2(fast_ex2(B_LOG2E * v[i].x), fast_ex2(B_LOG2E * v[i].y));
        *(float2*)(d + 2) = make_float2(fast_ex2(B_LOG2E * v[i].z), fast_ex2(B_LOG2E * v[i].w));
    }
}

// ── conv: direct-LDG 5x5, packed FFMA2, no smem/barriers ─────────────────
__global__ __launch_bounds__(NT, 6)
void morph_conv_kernel(float* __restrict__ out)
{
    const int img  = blockIdx.y;
    const int c    = img & (CC - 1);
    const int t    = threadIdx.x;
    const int lane = t & 31;
    const int r0   = t >> 5;
    const int sy   = blockIdx.x * 16 + r0 * 4;   // first output row
    const int cg   = lane;                       // output cols 4*cg..4*cg+3

    const float* Ei = g_E + (size_t)img * EIMG;

    // taps (uniform LDG.64, L1-broadcast; register-resident thereafter)
    float2 a2[KK * KK];
    #pragma unroll
    for (int i = 0; i < KK * KK; i++) a2[i] = g_A2[c][i];

    float2 acc01[4], acc23[4];
    #pragma unroll
    for (int q = 0; q < 4; q++) {
        acc01[q] = make_float2(0.f, 0.f);
        acc23[q] = make_float2(0.f, 0.f);
    }

    // out rows sy..sy+3 need E rows sy..sy+7; window E cols 4cg..4cg+7
    // (E is padded, so loads are unconditional and 16B-aligned)
    #pragma unroll
    for (int rr = 0; rr < 8; rr++) {
        const float* row = &Ei[(sy + rr) * EP + 4 * cg];
        float4 q0 = *(const float4*)row;
        float4 q1 = *(const float4*)(row + 4);
        float2 p[7];
        p[0] = make_float2(q0.x, q0.y);
        p[1] = make_float2(q0.y, q0.z);
        p[2] = make_float2(q0.z, q0.w);
        p[3] = make_float2(q0.w, q1.x);
        p[4] = make_float2(q1.x, q1.y);
        p[5] = make_float2(q1.y, q1.z);
        p[6] = make_float2(q1.z, q1.w);
        #pragma unroll
        for (int ky = 0; ky < KK; ky++) {
            int vo = rr - ky;
            if (vo >= 0 && vo < 4) {
                #pragma unroll
                for (int kx = 0; kx < KK; kx++) {
                    acc01[vo] = ffma2(a2[ky * KK + kx], p[kx],     acc01[vo]);
                    acc23[vo] = ffma2(a2[ky * KK + kx], p[kx + 2], acc23[vo]);
                }
            }
        }
    }

    float* oi = out + (size_t)img * (HH * WW);
    #pragma unroll
    for (int q = 0; q < 4; q++) {
        float4 o;
        o.x = fast_lg2(acc01[q].x) * LN2_OVER_B;
        o.y = fast_lg2(acc01[q].y) * LN2_OVER_B;
        o.z = fast_lg2(acc23[q].x) * LN2_OVER_B;
        o.w = fast_lg2(acc23[q].y) * LN2_OVER_B;
        *(float4*)&oi[(sy + q) * WW + 4 * cg] = o;
    }
}

extern "C" void kernel_launch(void* const* d_in, const int* in_sizes, int n_in,
                              void* d_out, int out_size)
{
    const float* x  = (const float*)d_in[0];   // (4, 64, 128, 128) fp32
    const float* wy = (const float*)d_in[1];   // (64, 5, 5) fp32
    float* out = (float*)d_out;                // (4, 64, 128, 128) fp32

    dim3 grid(HH / 16, BB * CC);               // (8, 256) = 2048 blocks each
    morph_prep_kernel<<<grid, NT>>>(x, wy);
    morph_conv_kernel<<<grid, NT>>>(out);
}

// round 13
// speedup vs baseline: 1.5731x; 1.5731x over previous
#include <cuda_runtime.h>

// Soft 5x5 dilation:  y = logsumexp((w + patch)*B)/B
// Factored:  y = log2( conv5x5( exp2(c*x), exp2(c*w) ) ) * (ln2/B),  c = B*log2e
// Zero-pad of x -> pad value 1.0 in exp-space.
// R5 champion structure + 9-CTA/SM reg cap + OOB predicates only on the two
// rows that can actually be out of bounds (p=0, p=4).

#define KK 5
#define BETA 15.0f
#define CC 64
#define HH 128
#define WW 128
#define BB 4

#define TILE_H 16
#define SROWS (TILE_H + 4)      // 20
#define SCOLS 132               // smem col = input col + 2
#define NT 128

#define B_LOG2E (BETA * 1.44269504f)
#define LN2_OVER_B (0.69314718f / BETA)

typedef unsigned long long u64;

__device__ __forceinline__ float fast_ex2(float v) {
    float r; asm("ex2.approx.ftz.f32 %0, %1;" : "=f"(r) : "f"(v)); return r;
}
__device__ __forceinline__ float fast_lg2(float v) {
    float r; asm("lg2.approx.ftz.f32 %0, %1;" : "=f"(r) : "f"(v)); return r;
}

union F2U { float2 f; u64 u; };
__device__ __forceinline__ float2 ffma2(float2 a, float2 b, float2 c) {
    F2U A, B, C, D; A.f = a; B.f = b; C.f = c;
    asm("fma.rn.f32x2 %0, %1, %2, %3;" : "=l"(D.u) : "l"(A.u), "l"(B.u), "l"(C.u));
    return D.f;
}

__global__ __launch_bounds__(NT, 9)
void morph_soft_dilate_kernel(const float* __restrict__ x,
                              const float* __restrict__ wy,
                              float* __restrict__ out)
{
    __shared__ float sE[SROWS][SCOLS];   // 10560 B
    __shared__ float sA[32];

    const int img   = blockIdx.y;          // b*C + c
    const int c     = img & (CC - 1);
    const int tileY = blockIdx.x * TILE_H;
    const int t     = threadIdx.x;
    const int lane  = t & 31;
    const int r0    = t >> 5;

    const float* xi = x + (size_t)img * (HH * WW);

    // hoisted LDG batch (MLP=5). Rows p=1..3 are always in-bounds
    // (tileY+r0+2 .. tileY+r0+13 for all tiles); only p=0 / p=4 can be OOB.
    float4 v[5];
    const bool ok0 = (tileY + r0 - 2) >= 0;
    const bool ok4 = (tileY + r0 + 14) < HH;
    if (ok0) v[0] = *(const float4*)&xi[(tileY + r0 - 2) * WW + 4 * lane];
    #pragma unroll
    for (int p = 1; p < 4; p++)
        v[p] = *(const float4*)&xi[(tileY + r0 + 4 * p - 2) * WW + 4 * lane];
    if (ok4) v[4] = *(const float4*)&xi[(tileY + r0 + 14) * WW + 4 * lane];

    // setup overlapping LDG latency
    if (t < KK * KK)
        sA[t] = fast_ex2(B_LOG2E * wy[c * KK * KK + t]);
    if (t < 40) {                       // halo cols 0,1,130,131 for all 20 rows
        int r  = t >> 1;
        int cb = (t & 1) ? 130 : 0;
        sE[r][cb]     = 1.0f;
        sE[r][cb + 1] = 1.0f;
    }
    {                                   // pad rows at true image edges only
        float4* sp = (float4*)&sE[0][0];
        const float4 ones = make_float4(1.f, 1.f, 1.f, 1.f);
        if (tileY == 0 && t < 66)              sp[t] = ones;        // rows 0,1
        if (tileY == HH - TILE_H && t < 66)    sp[594 + t] = ones;  // rows 18,19
    }

    // convert + STS
    #pragma unroll
    for (int p = 0; p < 5; p++) {
        bool wr = (p == 0) ? ok0 : (p == 4) ? ok4 : true;
        if (wr) {
            int r = r0 + 4 * p;
            float2 e01 = make_float2(fast_ex2(B_LOG2E * v[p].x), fast_ex2(B_LOG2E * v[p].y));
            float2 e23 = make_float2(fast_ex2(B_LOG2E * v[p].z), fast_ex2(B_LOG2E * v[p].w));
            *(float2*)&sE[r][4 * lane + 2] = e01;
            *(float2*)&sE[r][4 * lane + 4] = e23;
        }
    }
    __syncthreads();

    // taps duplicated into both f32x2 lanes (register-resident)
    float2 a2[KK * KK];
    #pragma unroll
    for (int i = 0; i < KK * KK; i++) { float w0 = sA[i]; a2[i] = make_float2(w0, w0); }

    const int cg = lane;            // output cols 4*cg .. 4*cg+3
    const int sy = r0 * 4;          // output rows tileY+sy .. +3

    float2 acc01[4], acc23[4];
    #pragma unroll
    for (int q = 0; q < 4; q++) {
        acc01[q] = make_float2(0.f, 0.f);
        acc23[q] = make_float2(0.f, 0.f);
    }

    // 8 smem rows feed the 4x4 patch; per row: 2x LDS.128, packed FFMA2
    #pragma unroll
    for (int rr = 0; rr < 8; rr++) {
        float4 q0 = *(const float4*)&sE[sy + rr][4 * cg];
        float4 q1 = *(const float4*)&sE[sy + rr][4 * cg + 4];
        float2 p[7];
        p[0] = make_float2(q0.x, q0.y);
        p[1] = make_float2(q0.y, q0.z);
        p[2] = make_float2(q0.z, q0.w);
        p[3] = make_float2(q0.w, q1.x);
        p[4] = make_float2(q1.x, q1.y);
        p[5] = make_float2(q1.y, q1.z);
        p[6] = make_float2(q1.z, q1.w);
        #pragma unroll
        for (int ky = 0; ky < KK; ky++) {
            int vo = rr - ky;
            if (vo >= 0 && vo < 4) {
                #pragma unroll
                for (int kx = 0; kx < KK; kx++) {
                    acc01[vo] = ffma2(a2[ky * KK + kx], p[kx],     acc01[vo]);
                    acc23[vo] = ffma2(a2[ky * KK + kx], p[kx + 2], acc23[vo]);
                }
            }
        }
    }

    float* oi = out + (size_t)img * (HH * WW);
    #pragma unroll
    for (int q = 0; q < 4; q++) {
        float4 o;
        o.x = fast_lg2(acc01[q].x) * LN2_OVER_B;
        o.y = fast_lg2(acc01[q].y) * LN2_OVER_B;
        o.z = fast_lg2(acc23[q].x) * LN2_OVER_B;
        o.w = fast_lg2(acc23[q].y) * LN2_OVER_B;
        *(float4*)&oi[(tileY + sy + q) * WW + 4 * cg] = o;
    }
}

extern "C" void kernel_launch(void* const* d_in, const int* in_sizes, int n_in,
                              void* d_out, int out_size)
{
    const float* x  = (const float*)d_in[0];   // (4, 64, 128, 128) fp32
    const float* wy = (const float*)d_in[1];   // (64, 5, 5) fp32
    float* out = (float*)d_out;                // (4, 64, 128, 128) fp32

    dim3 grid(HH / TILE_H, BB * CC);           // (8, 256) = 2048 blocks
    morph_soft_dilate_kernel<<<grid, NT>>>(x, wy, out);
}